// round 6
// baseline (speedup 1.0000x reference)
#include <cuda_runtime.h>

// Fused upsample2x-bilinear -> affine_grid -> grid_sample_bilinear.
// Separable composition: output = 3x3 weighted sum over ORIGINAL image.
// R6: NHWC repack so warp lanes = channels. Each 3x3 tap is ONE LDG.32
// touching exactly one 128B line (32 channels). Taps/weights computed once
// per output point (lane-parallel into SMEM table), outputs transposed back
// to NCHW through padded SMEM for coalesced 128B stores.

#define N_   8
#define C_   32
#define HI   256
#define WI   256
#define HU   512
#define WU   512

// NHWC scratch: 8*256*256*32 floats = 67 MB (device global: allocation-free)
__device__ float4 g_nhwc4[N_ * HI * WI * (C_ / 4)];

// ---------------- prepass: NCHW -> NHWC tiled transpose ----------------
__global__ void __launch_bounds__(256)
transpose_nhwc(const float* __restrict__ x) {
    __shared__ float t[C_][33];
    int lane = threadIdx.x & 31;
    int wp   = threadIdx.x >> 5;          // 8 warps
    int bh = blockIdx.x;                   // n*HI + h
    int w0 = blockIdx.y << 5;              // w tile origin (8 tiles)
    int n = bh >> 8, h = bh & 255;

    const float* ip = x + (((long long)n * C_) * HI + h) * WI + w0;
    #pragma unroll
    for (int k = 0; k < 4; k++) {
        int c = (k << 3) + wp;
        t[c][lane] = ip[(long long)c * (HI * WI) + lane];   // coalesced read
    }
    __syncthreads();

    float* op = (float*)g_nhwc4 + (((long long)n * HI + h) * WI + w0) * C_;
    #pragma unroll
    for (int k = 0; k < 4; k++) {
        int wl = (k << 3) + wp;
        op[wl * C_ + lane] = t[lane][wl];                   // coalesced write
    }
}

// ---------------- main fused kernel ----------------
__device__ __forceinline__ void axis_taps(float f, int U, int O,
                                          int& base, float w[3]) {
    float f0 = floorf(f);
    int   i0 = (int)f0;
    float wf = f - f0;

    w[0] = 0.f; w[1] = 0.f; w[2] = 0.f;
    base = 0;

    #pragma unroll
    for (int k = 0; k < 2; k++) {
        int   t  = i0 + k;
        float Wk = (k == 0) ? (1.0f - wf) : wf;
        Wk = (t >= 0 && t < U) ? Wk : 0.0f;          // zero-padding validity
        int tc = min(max(t, 0), U - 1);
        float s  = fmaxf((float)tc * 0.5f - 0.25f, 0.0f);  // upsample source
        int   o0 = (int)s;
        float wu = s - (float)o0;
        int   o1 = min(o0 + 1, O - 1);
        if (k == 0) base = o0;                       // taps are monotone
        w[o0 - base] += Wk * (1.0f - wu);
        w[o1 - base] += Wk * wu;
    }
}

__global__ void __launch_bounds__(256)
fused_gather_nhwc(const float* __restrict__ theta,
                  float* __restrict__ out) {
    __shared__ int   offs[8][9][32];    // [warp][tap][point]
    __shared__ float wts [8][9][32];
    __shared__ float obuf[8][C_][33];   // [warp][channel][point], padded

    int w    = threadIdx.x >> 5;
    int lane = threadIdx.x & 31;
    int wid  = blockIdx.x * 8 + w;
    int n   = wid >> 13;                 // 8192 warps per image
    int r   = wid & 8191;
    int yo  = r >> 4;                    // 512 rows
    int xo0 = (r & 15) << 5;             // 16 x-segments of 32

    // ---- phase 1: lane computes taps for ITS OWN point (xo0+lane, yo) ----
    {
        int xo = xo0 + lane;
        float gxn = (2.0f * (float)xo + 1.0f) / (float)WU - 1.0f;
        float gyn = (2.0f * (float)yo + 1.0f) / (float)HU - 1.0f;
        const float* th = theta + n * 6;
        float gox = __ldg(th + 0) * gxn + __ldg(th + 1) * gyn + __ldg(th + 2);
        float goy = __ldg(th + 3) * gxn + __ldg(th + 4) * gyn + __ldg(th + 5);
        float ix = ((gox + 1.0f) * (float)WU - 1.0f) * 0.5f;
        float iy = ((goy + 1.0f) * (float)HU - 1.0f) * 0.5f;

        int by, bx;
        float wy[3], wx[3];
        axis_taps(iy, HU, HI, by, wy);   // oob -> weights all zero, offsets clamped
        axis_taps(ix, WU, WI, bx, wx);

        int ro[3], co[3];
        #pragma unroll
        for (int i = 0; i < 3; i++) {
            ro[i] = min(by + i, HI - 1) * (WI * C_);
            co[i] = min(bx + i, WI - 1) * C_;
        }
        #pragma unroll
        for (int i = 0; i < 3; i++)
            #pragma unroll
            for (int j = 0; j < 3; j++) {
                offs[w][i * 3 + j][lane] = ro[i] + co[j];
                wts [w][i * 3 + j][lane] = wy[i] * wx[j];
            }
    }
    __syncwarp();

    // ---- phase 2: warp loops 32 points; lane = channel ----
    const float* xp = (const float*)g_nhwc4
                      + (long long)n * (HI * WI * C_) + lane;
    #pragma unroll 4
    for (int p = 0; p < 32; p++) {
        float v = 0.0f;
        #pragma unroll
        for (int k = 0; k < 9; k++)
            v = fmaf(wts[w][k][p], __ldg(xp + offs[w][k][p]), v);
        obuf[w][lane][p] = v;
    }
    __syncwarp();

    // ---- phase 3: coalesced NCHW stores (one 128B line per channel) ----
    float* outp = out + ((long long)n * C_) * (HU * WU)
                      + (long long)yo * WU + xo0;
    #pragma unroll 4
    for (int c = 0; c < C_; c++)
        outp[(long long)c * (HU * WU) + lane] = obuf[w][c][lane];
}

extern "C" void kernel_launch(void* const* d_in, const int* in_sizes, int n_in,
                              void* d_out, int out_size) {
    const float* x     = (const float*)d_in[0];
    const float* theta = (const float*)d_in[1];
    float*       out   = (float*)d_out;

    dim3 tg(N_ * HI, WI / 32);           // (2048, 8) tiles of 32c x 32w
    transpose_nhwc<<<tg, 256>>>(x);

    // 65536 warps: one warp per 32-point output row segment (all 32 channels)
    fused_gather_nhwc<<<8192, 256>>>(theta, out);
}

// round 7
// speedup vs baseline: 1.7430x; 1.7430x over previous
#include <cuda_runtime.h>

// Fused upsample2x-bilinear -> affine_grid -> grid_sample_bilinear.
// Separable composition: output = 3x3 weighted sum over ORIGINAL image.
// R7: NHWC repack (lane quads = channels). Each pass: 4 points x 32 channels
// via 9 LDG.128 (minimal 9 lines/point). Tap data moved by SHFL, not LDS.

#define N_   8
#define C_   32
#define HI   256
#define WI   256
#define HU   512
#define WU   512

// NHWC scratch: 8*256*256*32 floats = 67 MB (device global: allocation-free)
__device__ float4 g_nhwc4[N_ * HI * WI * (C_ / 4)];

// ---------------- prepass: NCHW -> NHWC tiled transpose ----------------
__global__ void __launch_bounds__(256)
transpose_nhwc(const float* __restrict__ x) {
    __shared__ float t[C_][33];
    int lane = threadIdx.x & 31;
    int wp   = threadIdx.x >> 5;          // 8 warps
    int bh = blockIdx.x;                   // n*HI + h
    int w0 = blockIdx.y << 5;              // w tile origin (8 tiles)
    int n = bh >> 8, h = bh & 255;

    const float* ip = x + (((long long)n * C_) * HI + h) * WI + w0;
    #pragma unroll
    for (int k = 0; k < 4; k++) {
        int c = (k << 3) + wp;
        t[c][lane] = ip[(long long)c * (HI * WI) + lane];   // coalesced read
    }
    __syncthreads();

    float* op = (float*)g_nhwc4 + (((long long)n * HI + h) * WI + w0) * C_;
    #pragma unroll
    for (int k = 0; k < 4; k++) {
        int wl = (k << 3) + wp;
        op[wl * C_ + lane] = t[lane][wl];                   // coalesced write
    }
}

// ---------------- main fused kernel ----------------
__device__ __forceinline__ void axis_taps(float f, int U, int O,
                                          int& base, float w[3]) {
    float f0 = floorf(f);
    int   i0 = (int)f0;
    float wf = f - f0;

    w[0] = 0.f; w[1] = 0.f; w[2] = 0.f;
    base = 0;

    #pragma unroll
    for (int k = 0; k < 2; k++) {
        int   t  = i0 + k;
        float Wk = (k == 0) ? (1.0f - wf) : wf;
        Wk = (t >= 0 && t < U) ? Wk : 0.0f;          // zero-padding validity
        int tc = min(max(t, 0), U - 1);
        float s  = fmaxf((float)tc * 0.5f - 0.25f, 0.0f);  // upsample source
        int   o0 = (int)s;
        float wu = s - (float)o0;
        int   o1 = min(o0 + 1, O - 1);
        if (k == 0) base = o0;                       // taps are monotone
        w[o0 - base] += Wk * (1.0f - wu);
        w[o1 - base] += Wk * wu;
    }
}

__global__ void __launch_bounds__(256)
fused_gather_nhwc(const float* __restrict__ theta,
                  float* __restrict__ out) {
    __shared__ float obuf[8][C_][33];   // [warp][channel][point], pad 33

    const unsigned FULL = 0xFFFFFFFFu;
    int w    = threadIdx.x >> 5;
    int lane = threadIdx.x & 31;
    int wid  = blockIdx.x * 8 + w;
    int n   = wid >> 13;                 // 8192 warps per image
    int r   = wid & 8191;
    int yo  = r >> 4;                    // 512 rows
    int xo0 = (r & 15) << 5;             // 16 x-segments of 32

    float* outp = out + ((long long)n * C_) * (HU * WU)
                      + (long long)yo * WU + xo0;

    // ---- per-lane taps for point (xo0+lane, yo) ----
    int ro4[3], co4[3];
    float wy[3], wx[3];
    int z;                               // 1 if this point contributes zero
    {
        int xo = xo0 + lane;
        float gxn = (2.0f * (float)xo + 1.0f) / (float)WU - 1.0f;
        float gyn = (2.0f * (float)yo + 1.0f) / (float)HU - 1.0f;
        const float* th = theta + n * 6;
        float gox = __ldg(th + 0) * gxn + __ldg(th + 1) * gyn + __ldg(th + 2);
        float goy = __ldg(th + 3) * gxn + __ldg(th + 4) * gyn + __ldg(th + 5);
        float ix = ((gox + 1.0f) * (float)WU - 1.0f) * 0.5f;
        float iy = ((goy + 1.0f) * (float)HU - 1.0f) * 0.5f;

        int by, bx;
        axis_taps(iy, HU, HI, by, wy);   // indices always clamped into range
        axis_taps(ix, WU, WI, bx, wx);

        #pragma unroll
        for (int i = 0; i < 3; i++) {
            ro4[i] = min(by + i, HI - 1) * (WI * (C_ / 4));  // float4 units
            co4[i] = min(bx + i, WI - 1) * (C_ / 4);
        }
        z = ((wy[0] + wy[1] + wy[2]) == 0.0f) ||
            ((wx[0] + wx[1] + wx[2]) == 0.0f);
    }

    // ---- whole warp out of bounds: direct zero stores ----
    if (__all_sync(FULL, z)) {
        #pragma unroll 8
        for (int c = 0; c < C_; c++)
            outp[(long long)c * (HU * WU) + lane] = 0.0f;
        return;
    }

    // ---- 8 passes of 4 points x 32 channels ----
    int g  = lane >> 3;                  // point within pass
    int lc = lane & 7;                   // channel quad
    const float4* xp = g_nhwc4 + (long long)n * (HI * WI * (C_ / 4)) + lc;

    #pragma unroll 2
    for (int pass = 0; pass < 8; pass++) {
        int src = (pass << 2) | g;
        int R0 = __shfl_sync(FULL, ro4[0], src);
        int R1 = __shfl_sync(FULL, ro4[1], src);
        int R2 = __shfl_sync(FULL, ro4[2], src);
        int K0 = __shfl_sync(FULL, co4[0], src);
        int K1 = __shfl_sync(FULL, co4[1], src);
        int K2 = __shfl_sync(FULL, co4[2], src);
        float Y0 = __shfl_sync(FULL, wy[0], src);
        float Y1 = __shfl_sync(FULL, wy[1], src);
        float Y2 = __shfl_sync(FULL, wy[2], src);
        float X0 = __shfl_sync(FULL, wx[0], src);
        float X1 = __shfl_sync(FULL, wx[1], src);
        float X2 = __shfl_sync(FULL, wx[2], src);
        int   zs = __shfl_sync(FULL, z, src);

        float4 acc = make_float4(0.f, 0.f, 0.f, 0.f);
        if (!__all_sync(FULL, zs)) {
            int   Rs[3] = {R0, R1, R2};
            int   Ks[3] = {K0, K1, K2};
            float Ys[3] = {Y0, Y1, Y2};
            float Xs[3] = {X0, X1, X2};
            #pragma unroll
            for (int i = 0; i < 3; i++)
                #pragma unroll
                for (int jj = 0; jj < 3; jj++) {
                    float wij = Ys[i] * Xs[jj];
                    float4 t = __ldg(xp + Rs[i] + Ks[jj]);
                    acc.x = fmaf(wij, t.x, acc.x);
                    acc.y = fmaf(wij, t.y, acc.y);
                    acc.z = fmaf(wij, t.z, acc.z);
                    acc.w = fmaf(wij, t.w, acc.w);
                }
        }

        int p  = (pass << 2) | g;
        int cb = lc << 2;
        obuf[w][cb + 0][p] = acc.x;      // bank = (4lc+g)+const: conflict-free
        obuf[w][cb + 1][p] = acc.y;
        obuf[w][cb + 2][p] = acc.z;
        obuf[w][cb + 3][p] = acc.w;
    }
    __syncwarp();

    // ---- coalesced NCHW stores (one 128B line per channel) ----
    #pragma unroll 4
    for (int c = 0; c < C_; c++)
        outp[(long long)c * (HU * WU) + lane] = obuf[w][c][lane];
}

extern "C" void kernel_launch(void* const* d_in, const int* in_sizes, int n_in,
                              void* d_out, int out_size) {
    const float* x     = (const float*)d_in[0];
    const float* theta = (const float*)d_in[1];
    float*       out   = (float*)d_out;

    dim3 tg(N_ * HI, WI / 32);           // (2048, 8) tiles of 32c x 32w
    transpose_nhwc<<<tg, 256>>>(x);

    // 65536 warps: one warp per 32-point output row segment (all 32 channels)
    fused_gather_nhwc<<<8192, 256>>>(theta, out);
}